// round 3
// baseline (speedup 1.0000x reference)
#include <cuda_runtime.h>

// ---------------------------------------------------------------------------
// Collapsed TemporalGNN (H0 == 0 in the scan; R gate dead):
//   y    = A_hat x           (pull-gather via per-dst buckets, no atomics)
//   Hn   = 0.5*(1 - tanh((y@Mz + cz)/2)) * tanh(y@Mh + ch)
//   acc  = sum_t p_t * Hn ;  out = relu(acc) @ head_w + head_b
// Mz/cz pre-scaled by 0.5; p pre-scaled by 0.5 at setup.
// ---------------------------------------------------------------------------

#define NB 4
#define NN 30000
#define NT 12
#define NH 32
#define NO 12
#define NE 240000
#define NODE_W 24               /* F_IN(2) * T(12) floats per (b,node) */
#define CAP 64                  /* bucket capacity >> max in-degree (~30) */
#define DEG_BLOCKS ((NN + 255) / 256)

__device__ float g_deg[NN];
__device__ int   g_cnt[NN];
__device__ uint2 g_bkt[(size_t)NN * CAP];     // (src, bitcast norm)
__device__ float g_y[(size_t)NB * NN * NODE_W];
__device__ float g_Mz[2 * NH];
__device__ float g_Mh[2 * NH];
__device__ float g_cz[NH];
__device__ float g_ch[NH];
__device__ float g_p[NT];

__device__ __forceinline__ float tanh_approx(float x) {
    float r;
    asm("tanh.approx.f32 %0, %1;" : "=f"(r) : "f"(x));
    return r;
}

// Blocks [0, DEG_BLOCKS): deg = 1 (self loop), cnt = 0.
// Block DEG_BLOCKS: fused-weight setup + softmax.
__global__ void k_init(const float* __restrict__ att,
                       const float* __restrict__ czw, const float* __restrict__ czb,
                       const float* __restrict__ lzw, const float* __restrict__ lzb,
                       const float* __restrict__ chw, const float* __restrict__ chb,
                       const float* __restrict__ lhw, const float* __restrict__ lhb) {
    if (blockIdx.x < DEG_BLOCKS) {
        int i = blockIdx.x * 256 + threadIdx.x;
        if (i < NN) { g_deg[i] = 1.0f; g_cnt[i] = 0; }
        return;
    }
    int lane = threadIdx.x & 31;
    int warp = threadIdx.x >> 5;

    if (threadIdx.x == 0) {
        float m = -1e30f;
        for (int i = 0; i < NT; i++) m = fmaxf(m, att[i]);
        float e[NT], s = 0.f;
        for (int i = 0; i < NT; i++) { e[i] = __expf(att[i] - m); s += e[i]; }
        float inv = 0.5f / s;                    // fold the 0.5 of (1-tz)/2 here
        for (int i = 0; i < NT; i++) g_p[i] = e[i] * inv;
    }

#pragma unroll
    for (int i = warp; i < 2 * NH; i += 8) {
        int gate = i >> 5;                       // 0 = z gate, 1 = h gate
        int h = i & 31;
        const float* cw = gate ? chw : czw;
        const float* cb = gate ? chb : czb;
        const float* lw = gate ? lhw : lzw;
        const float* lb = gate ? lhb : lzb;
        float w = lw[lane * NH + h];             // only first NH rows matter (H0=0)
        float m0 = cw[lane] * w;
        float m1 = cw[NH + lane] * w;
        float c  = cb[lane] * w;
#pragma unroll
        for (int off = 16; off; off >>= 1) {
            m0 += __shfl_xor_sync(0xffffffffu, m0, off);
            m1 += __shfl_xor_sync(0xffffffffu, m1, off);
            c  += __shfl_xor_sync(0xffffffffu, c, off);
        }
        if (lane == 0) {
            c += lb[h];
            if (gate == 0) {
                g_Mz[h] = 0.5f * m0; g_Mz[NH + h] = 0.5f * m1; g_cz[h] = 0.5f * c;
            } else {
                g_Mh[h] = m0; g_Mh[NH + h] = m1; g_ch[h] = c;
            }
        }
    }
}

__global__ void k_deg(const int* __restrict__ ei) {
    int e = blockIdx.x * blockDim.x + threadIdx.x;
    if (e < NE) atomicAdd(&g_deg[ei[NE + e]], 1.0f);
}

// After deg is final: fill per-dst buckets with (src, norm). One pass.
__global__ void k_fill(const int* __restrict__ ei) {
    int e = blockIdx.x * blockDim.x + threadIdx.x;
    if (e >= NE) return;
    int s = __ldg(ei + e);
    int d = __ldg(ei + NE + e);
    float norm = rsqrtf(g_deg[s]) * rsqrtf(g_deg[d]);
    int pos = atomicAdd(&g_cnt[d], 1);
    g_bkt[(size_t)d * CAP + pos] = make_uint2((unsigned)s, __float_as_uint(norm));
}

// Pull-gather: warp per (node, batch); 24 active lanes; lane j owns y[b,n,j].
// No atomics, y written exactly once (self-loop term fused in).
__global__ void __launch_bounds__(256)
k_gather(const float* __restrict__ x) {
    int w    = blockIdx.x * 8 + (threadIdx.x >> 5);
    int lane = threadIdx.x & 31;
    if (w >= NB * NN || lane >= NODE_W) return;
    int n = w >> 2;          // 4 consecutive warps share one node's bucket
    int b = w & 3;

    float dval = g_deg[n];
    int   cnt  = g_cnt[n];
    const uint2* bp = g_bkt + (size_t)n * CAP;

    size_t base = ((size_t)b * NN + n) * NODE_W;
    float acc = __ldg(x + base + lane) * __fdividef(1.0f, dval);  // self loop

    for (int e = 0; e < cnt; e++) {
        uint2 p = bp[e];                                   // lane-uniform load
        float norm = __uint_as_float(p.y);
        acc = fmaf(norm, __ldg(x + ((size_t)b * NN + p.x) * NODE_W + lane), acc);
    }
    g_y[base + lane] = acc;
}

// Pointwise collapse + head GEMV. One thread per (b, node).
// Per (t,h): 2 tanh.approx (MUFU) + 6 FMA. MUFU-roofline ~21us chip-wide.
__global__ void __launch_bounds__(256)
k_node(const float* __restrict__ hw, const float* __restrict__ hb,
       float* __restrict__ out) {
    __shared__ float s_Mz[2 * NH], s_Mh[2 * NH], s_cz[NH], s_ch[NH], s_p[NT];
    __shared__ float s_hw[NH * NO], s_hb[NO];
    int tid = threadIdx.x;
    for (int i = tid; i < 2 * NH; i += 256) { s_Mz[i] = g_Mz[i]; s_Mh[i] = g_Mh[i]; }
    if (tid < NH) { s_cz[tid] = g_cz[tid]; s_ch[tid] = g_ch[tid]; }
    if (tid < NT) s_p[tid] = g_p[tid];
    for (int i = tid; i < NH * NO; i += 256) s_hw[i] = hw[i];
    if (tid < NO) s_hb[tid] = hb[tid];
    __syncthreads();

    int gid = blockIdx.x * 256 + tid;
    if (gid >= NB * NN) return;

    float yv[NODE_W];
    const float4* yp4 = (const float4*)(g_y + (size_t)gid * NODE_W);
#pragma unroll
    for (int i = 0; i < NODE_W / 4; i++) {
        float4 v = yp4[i];
        yv[4 * i + 0] = v.x; yv[4 * i + 1] = v.y;
        yv[4 * i + 2] = v.z; yv[4 * i + 3] = v.w;
    }

    float acc[NH];
#pragma unroll
    for (int h = 0; h < NH; h++) acc[h] = 0.f;

#pragma unroll 1
    for (int t = 0; t < NT; t++) {
        float hp = s_p[t];                        // 0.5 * softmax prob
        float a  = yv[t];
        float bb = yv[NT + t];
#pragma unroll
        for (int h = 0; h < NH; h++) {
            float az = fmaf(a, s_Mz[h], fmaf(bb, s_Mz[NH + h], s_cz[h]));
            float ah = fmaf(a, s_Mh[h], fmaf(bb, s_Mh[NH + h], s_ch[h]));
            float tz = tanh_approx(az);           // tanh((y@Mz+cz)/2)
            float th = tanh_approx(ah);
            float u  = fmaf(-tz, th, th);         // (1 - tz) * th
            acc[h]   = fmaf(hp, u, acc[h]);
        }
    }

    float o[NO];
#pragma unroll
    for (int j = 0; j < NO; j++) o[j] = s_hb[j];
#pragma unroll
    for (int h = 0; h < NH; h++) {
        float r = fmaxf(acc[h], 0.f);
#pragma unroll
        for (int j = 0; j < NO; j++) o[j] = fmaf(r, s_hw[h * NO + j], o[j]);
    }
    float4* op4 = (float4*)(out + (size_t)gid * NO);
#pragma unroll
    for (int j = 0; j < NO / 4; j++)
        op4[j] = make_float4(o[4 * j], o[4 * j + 1], o[4 * j + 2], o[4 * j + 3]);
}

extern "C" void kernel_launch(void* const* d_in, const int* in_sizes, int n_in,
                              void* d_out, int out_size) {
    const float* x   = (const float*)d_in[0];
    const int*   ei  = (const int*)d_in[1];
    const float* att = (const float*)d_in[2];
    const float* czw = (const float*)d_in[3];
    const float* czb = (const float*)d_in[4];
    const float* lzw = (const float*)d_in[5];
    const float* lzb = (const float*)d_in[6];
    // d_in[7..10] = conv_r_*, lin_r_* : dead (H0 == 0 -> H0*R == 0)
    const float* chw = (const float*)d_in[11];
    const float* chb = (const float*)d_in[12];
    const float* lhw = (const float*)d_in[13];
    const float* lhb = (const float*)d_in[14];
    const float* hw  = (const float*)d_in[15];
    const float* hb  = (const float*)d_in[16];
    float* out = (float*)d_out;

    k_init<<<DEG_BLOCKS + 1, 256>>>(att, czw, czb, lzw, lzb, chw, chb, lhw, lhb);
    k_deg<<<(NE + 255) / 256, 256>>>(ei);
    k_fill<<<(NE + 255) / 256, 256>>>(ei);

    int nwarps = NB * NN;                 // warp per (node,batch)
    k_gather<<<(nwarps + 7) / 8, 256>>>(x);

    k_node<<<(NB * NN + 255) / 256, 256>>>(hw, hb, out);
}

// round 4
// speedup vs baseline: 1.1343x; 1.1343x over previous
#include <cuda_runtime.h>

// ---------------------------------------------------------------------------
// Collapsed TemporalGNN (H0 == 0 in the scan; R gate dead):
//   y    = A_hat x           (pull-gather via per-dst buckets, no atomics)
//   Hn   = 0.5*(1 - tanh((y@Mz + cz)/2)) * tanh(y@Mh + ch)
//   acc  = sum_t p_t * Hn ;  out = relu(acc) @ head_w + head_b
// Mz/cz pre-scaled by 0.5; p pre-scaled by 0.5 at setup.
// Gather: warp per node, all 4 batches, float4 per lane, unroll-4 buckets.
// ---------------------------------------------------------------------------

#define NB 4
#define NN 30000
#define NT 12
#define NH 32
#define NO 12
#define NE 240000
#define NODE_W 24               /* F_IN(2) * T(12) floats per (b,node) */
#define NQ (NODE_W / 4)         /* 6 float4 per (b,node) */
#define CAP 64                  /* bucket capacity >> max in-degree (~35) */
#define DEG_BLOCKS ((NN + 255) / 256)

__device__ float g_deg[NN];
__device__ int   g_cnt[NN];
__device__ uint2 g_bkt[(size_t)NN * CAP];     // (src, bitcast norm)
__device__ float g_y[(size_t)NB * NN * NODE_W];
__device__ float g_Mz[2 * NH];
__device__ float g_Mh[2 * NH];
__device__ float g_cz[NH];
__device__ float g_ch[NH];
__device__ float g_p[NT];

__device__ __forceinline__ float tanh_approx(float x) {
    float r;
    asm("tanh.approx.f32 %0, %1;" : "=f"(r) : "f"(x));
    return r;
}

// Blocks [0, DEG_BLOCKS): deg = 1 (self loop), cnt = 0.
// Block DEG_BLOCKS: fused-weight setup + softmax.
__global__ void k_init(const float* __restrict__ att,
                       const float* __restrict__ czw, const float* __restrict__ czb,
                       const float* __restrict__ lzw, const float* __restrict__ lzb,
                       const float* __restrict__ chw, const float* __restrict__ chb,
                       const float* __restrict__ lhw, const float* __restrict__ lhb) {
    if (blockIdx.x < DEG_BLOCKS) {
        int i = blockIdx.x * 256 + threadIdx.x;
        if (i < NN) { g_deg[i] = 1.0f; g_cnt[i] = 0; }
        return;
    }
    int lane = threadIdx.x & 31;
    int warp = threadIdx.x >> 5;

    if (threadIdx.x == 0) {
        float m = -1e30f;
        for (int i = 0; i < NT; i++) m = fmaxf(m, att[i]);
        float e[NT], s = 0.f;
        for (int i = 0; i < NT; i++) { e[i] = __expf(att[i] - m); s += e[i]; }
        float inv = 0.5f / s;                    // fold the 0.5 of (1-tz)/2 here
        for (int i = 0; i < NT; i++) g_p[i] = e[i] * inv;
    }

#pragma unroll
    for (int i = warp; i < 2 * NH; i += 8) {
        int gate = i >> 5;                       // 0 = z gate, 1 = h gate
        int h = i & 31;
        const float* cw = gate ? chw : czw;
        const float* cb = gate ? chb : czb;
        const float* lw = gate ? lhw : lzw;
        const float* lb = gate ? lhb : lzb;
        float w = lw[lane * NH + h];             // only first NH rows matter (H0=0)
        float m0 = cw[lane] * w;
        float m1 = cw[NH + lane] * w;
        float c  = cb[lane] * w;
#pragma unroll
        for (int off = 16; off; off >>= 1) {
            m0 += __shfl_xor_sync(0xffffffffu, m0, off);
            m1 += __shfl_xor_sync(0xffffffffu, m1, off);
            c  += __shfl_xor_sync(0xffffffffu, c, off);
        }
        if (lane == 0) {
            c += lb[h];
            if (gate == 0) {
                g_Mz[h] = 0.5f * m0; g_Mz[NH + h] = 0.5f * m1; g_cz[h] = 0.5f * c;
            } else {
                g_Mh[h] = m0; g_Mh[NH + h] = m1; g_ch[h] = c;
            }
        }
    }
}

__global__ void k_deg(const int* __restrict__ ei) {
    int e = blockIdx.x * blockDim.x + threadIdx.x;
    if (e < NE) atomicAdd(&g_deg[ei[NE + e]], 1.0f);
}

// After deg is final: fill per-dst buckets with (src, norm). One pass.
__global__ void k_fill(const int* __restrict__ ei) {
    int e = blockIdx.x * blockDim.x + threadIdx.x;
    if (e >= NE) return;
    int s = __ldg(ei + e);
    int d = __ldg(ei + NE + e);
    float norm = rsqrtf(g_deg[s]) * rsqrtf(g_deg[d]);
    int pos = atomicAdd(&g_cnt[d], 1);
    g_bkt[(size_t)d * CAP + pos] = make_uint2((unsigned)s, __float_as_uint(norm));
}

// Pad each bucket to a multiple of 4 with (src=0, norm=0) dummies so the
// gather loop needs no tail handling.
__global__ void k_pad() {
    int n = blockIdx.x * 256 + threadIdx.x;
    if (n >= NN) return;
    int c = g_cnt[n];
    int rc = (c + 3) & ~3;
    for (int i = c; i < rc; i++)
        g_bkt[(size_t)n * CAP + i] = make_uint2(0u, 0u);
}

// Pull-gather v2: one warp per NODE, covering all 4 batches.
// lane = b*6 + quad (24 active lanes); each lane owns one float4 of y.
// Bucket entries consumed 4 at a time via two uint4 loads -> MLP=4 gathers.
__global__ void __launch_bounds__(256)
k_gather(const float* __restrict__ x) {
    int n    = blockIdx.x * 8 + (threadIdx.x >> 5);
    int lane = threadIdx.x & 31;
    if (n >= NN) return;
    bool act = lane < 24;
    int q = lane % 6;
    int b = act ? (lane / 6) : 0;

    float inv = __fdividef(1.0f, g_deg[n]);
    int   cnt = g_cnt[n];
    const uint4* bp4 = (const uint4*)(g_bkt + (size_t)n * CAP);
    const float4* x4 = (const float4*)x;

    size_t self = ((size_t)b * NN + n) * NQ + q;
    float4 acc = make_float4(0.f, 0.f, 0.f, 0.f);
    if (act) {
        float4 xs = __ldg(x4 + self);
        acc.x = xs.x * inv; acc.y = xs.y * inv;
        acc.z = xs.z * inv; acc.w = xs.w * inv;
    }

    int rc = (cnt + 3) >> 2;                      // groups of 4 entries
    for (int g = 0; g < rc; g++) {
        uint4 pa = bp4[2 * g];                    // entries 4g, 4g+1 (uniform)
        uint4 pb = bp4[2 * g + 1];                // entries 4g+2, 4g+3
        if (act) {
            size_t rowb = (size_t)b * NN;
            float4 v0 = __ldg(x4 + (rowb + pa.x) * NQ + q);
            float4 v1 = __ldg(x4 + (rowb + pa.z) * NQ + q);
            float4 v2 = __ldg(x4 + (rowb + pb.x) * NQ + q);
            float4 v3 = __ldg(x4 + (rowb + pb.z) * NQ + q);
            float n0 = __uint_as_float(pa.y), n1 = __uint_as_float(pa.w);
            float n2 = __uint_as_float(pb.y), n3 = __uint_as_float(pb.w);
            acc.x = fmaf(n0, v0.x, acc.x); acc.y = fmaf(n0, v0.y, acc.y);
            acc.z = fmaf(n0, v0.z, acc.z); acc.w = fmaf(n0, v0.w, acc.w);
            acc.x = fmaf(n1, v1.x, acc.x); acc.y = fmaf(n1, v1.y, acc.y);
            acc.z = fmaf(n1, v1.z, acc.z); acc.w = fmaf(n1, v1.w, acc.w);
            acc.x = fmaf(n2, v2.x, acc.x); acc.y = fmaf(n2, v2.y, acc.y);
            acc.z = fmaf(n2, v2.z, acc.z); acc.w = fmaf(n2, v2.w, acc.w);
            acc.x = fmaf(n3, v3.x, acc.x); acc.y = fmaf(n3, v3.y, acc.y);
            acc.z = fmaf(n3, v3.z, acc.z); acc.w = fmaf(n3, v3.w, acc.w);
        }
    }
    if (act) ((float4*)g_y)[self] = acc;
}

// Pointwise collapse + head GEMV. One thread per (b, node).
// Per (t,h): 2 tanh.approx (MUFU) + 6 FMA. MUFU-roofline ~21us chip-wide.
__global__ void __launch_bounds__(256)
k_node(const float* __restrict__ hw, const float* __restrict__ hb,
       float* __restrict__ out) {
    __shared__ float s_Mz[2 * NH], s_Mh[2 * NH], s_cz[NH], s_ch[NH], s_p[NT];
    __shared__ float s_hw[NH * NO], s_hb[NO];
    int tid = threadIdx.x;
    for (int i = tid; i < 2 * NH; i += 256) { s_Mz[i] = g_Mz[i]; s_Mh[i] = g_Mh[i]; }
    if (tid < NH) { s_cz[tid] = g_cz[tid]; s_ch[tid] = g_ch[tid]; }
    if (tid < NT) s_p[tid] = g_p[tid];
    for (int i = tid; i < NH * NO; i += 256) s_hw[i] = hw[i];
    if (tid < NO) s_hb[tid] = hb[tid];
    __syncthreads();

    int gid = blockIdx.x * 256 + tid;
    if (gid >= NB * NN) return;

    float yv[NODE_W];
    const float4* yp4 = (const float4*)(g_y + (size_t)gid * NODE_W);
#pragma unroll
    for (int i = 0; i < NQ; i++) {
        float4 v = yp4[i];
        yv[4 * i + 0] = v.x; yv[4 * i + 1] = v.y;
        yv[4 * i + 2] = v.z; yv[4 * i + 3] = v.w;
    }

    float acc[NH];
#pragma unroll
    for (int h = 0; h < NH; h++) acc[h] = 0.f;

#pragma unroll 1
    for (int t = 0; t < NT; t++) {
        float hp = s_p[t];                        // 0.5 * softmax prob
        float a  = yv[t];
        float bb = yv[NT + t];
#pragma unroll
        for (int h = 0; h < NH; h++) {
            float az = fmaf(a, s_Mz[h], fmaf(bb, s_Mz[NH + h], s_cz[h]));
            float ah = fmaf(a, s_Mh[h], fmaf(bb, s_Mh[NH + h], s_ch[h]));
            float tz = tanh_approx(az);           // tanh((y@Mz+cz)/2)
            float th = tanh_approx(ah);
            float u  = fmaf(-tz, th, th);         // (1 - tz) * th
            acc[h]   = fmaf(hp, u, acc[h]);
        }
    }

    float o[NO];
#pragma unroll
    for (int j = 0; j < NO; j++) o[j] = s_hb[j];
#pragma unroll
    for (int h = 0; h < NH; h++) {
        float r = fmaxf(acc[h], 0.f);
#pragma unroll
        for (int j = 0; j < NO; j++) o[j] = fmaf(r, s_hw[h * NO + j], o[j]);
    }
    float4* op4 = (float4*)(out + (size_t)gid * NO);
#pragma unroll
    for (int j = 0; j < NO / 4; j++)
        op4[j] = make_float4(o[4 * j], o[4 * j + 1], o[4 * j + 2], o[4 * j + 3]);
}

extern "C" void kernel_launch(void* const* d_in, const int* in_sizes, int n_in,
                              void* d_out, int out_size) {
    const float* x   = (const float*)d_in[0];
    const int*   ei  = (const int*)d_in[1];
    const float* att = (const float*)d_in[2];
    const float* czw = (const float*)d_in[3];
    const float* czb = (const float*)d_in[4];
    const float* lzw = (const float*)d_in[5];
    const float* lzb = (const float*)d_in[6];
    // d_in[7..10] = conv_r_*, lin_r_* : dead (H0 == 0 -> H0*R == 0)
    const float* chw = (const float*)d_in[11];
    const float* chb = (const float*)d_in[12];
    const float* lhw = (const float*)d_in[13];
    const float* lhb = (const float*)d_in[14];
    const float* hw  = (const float*)d_in[15];
    const float* hb  = (const float*)d_in[16];
    float* out = (float*)d_out;

    k_init<<<DEG_BLOCKS + 1, 256>>>(att, czw, czb, lzw, lzb, chw, chb, lhw, lhb);
    k_deg<<<(NE + 255) / 256, 256>>>(ei);
    k_fill<<<(NE + 255) / 256, 256>>>(ei);
    k_pad<<<DEG_BLOCKS, 256>>>();

    k_gather<<<(NN + 7) / 8, 256>>>(x);           // warp per node

    k_node<<<(NB * NN + 255) / 256, 256>>>(hw, hb, out);
}

// round 5
// speedup vs baseline: 1.3515x; 1.1915x over previous
#include <cuda_runtime.h>
#include <cuda_fp16.h>

// ---------------------------------------------------------------------------
// Collapsed TemporalGNN (H0 == 0 in the scan; R gate dead):
//   y    = A_hat x           (pull-gather via per-dst buckets, no atomics)
//   Hn   = (1 + tanh(-(y@Mz + cz)/2)) * tanh(y@Mh + ch) * 0.5
//   acc  = sum_t p_t * Hn ;  out = relu(acc) @ head_w + head_b
// z-gate consts stored NEGATED and pre-scaled by 0.5; p pre-scaled by 0.5.
// k_node uses fma.rn.f32x2 (FFMA2) + tanh.approx.f16x2 packed over h-pairs.
// ---------------------------------------------------------------------------

#define NB 4
#define NN 30000
#define NT 12
#define NH 32
#define NO 12
#define NE 240000
#define NODE_W 24               /* F_IN(2) * T(12) floats per (b,node) */
#define NQ (NODE_W / 4)         /* 6 float4 per (b,node) */
#define CAP 64                  /* bucket capacity >> max in-degree (~30) */
#define DEG_BLOCKS ((NN + 255) / 256)

typedef unsigned long long u64;

__device__ float g_deg[NN];
__device__ int   g_cnt[NN];
__device__ uint2 g_bkt[(size_t)NN * CAP];     // (src, bitcast norm)
__device__ float g_y[(size_t)NB * NN * NODE_W];
__device__ float g_Mz[2 * NH];                // NEGATED, x0.5
__device__ float g_Mh[2 * NH];
__device__ float g_cz[NH];                    // NEGATED, x0.5
__device__ float g_ch[NH];
__device__ float g_p[NT];                     // softmax * 0.5

// ---- packed-math helpers ----
__device__ __forceinline__ u64 pk(float lo, float hi) {
    u64 r; asm("mov.b64 %0, {%1, %2};" : "=l"(r) : "f"(lo), "f"(hi)); return r;
}
__device__ __forceinline__ void upk(u64 v, float& lo, float& hi) {
    asm("mov.b64 {%0, %1}, %2;" : "=f"(lo), "=f"(hi) : "l"(v));
}
__device__ __forceinline__ u64 fma2(u64 a, u64 b, u64 c) {
    u64 r; asm("fma.rn.f32x2 %0, %1, %2, %3;" : "=l"(r) : "l"(a), "l"(b), "l"(c));
    return r;
}
__device__ __forceinline__ unsigned cvt2(float lo, float hi) {   // -> f16x2
    unsigned r; asm("cvt.rn.f16x2.f32 %0, %1, %2;" : "=r"(r) : "f"(hi), "f"(lo));
    return r;
}
__device__ __forceinline__ unsigned tanh2(unsigned x) {
    unsigned r; asm("tanh.approx.f16x2 %0, %1;" : "=r"(r) : "r"(x)); return r;
}
__device__ __forceinline__ unsigned hfma2u(unsigned a, unsigned b, unsigned c) {
    unsigned r; asm("fma.rn.f16x2 %0, %1, %2, %3;" : "=r"(r) : "r"(a), "r"(b), "r"(c));
    return r;
}

// Blocks [0, DEG_BLOCKS): deg = 1 (self loop), cnt = 0.
// Block DEG_BLOCKS: fused-weight setup + softmax.
__global__ void k_init(const float* __restrict__ att,
                       const float* __restrict__ czw, const float* __restrict__ czb,
                       const float* __restrict__ lzw, const float* __restrict__ lzb,
                       const float* __restrict__ chw, const float* __restrict__ chb,
                       const float* __restrict__ lhw, const float* __restrict__ lhb) {
    if (blockIdx.x < DEG_BLOCKS) {
        int i = blockIdx.x * 256 + threadIdx.x;
        if (i < NN) { g_deg[i] = 1.0f; g_cnt[i] = 0; }
        return;
    }
    int lane = threadIdx.x & 31;
    int warp = threadIdx.x >> 5;

    if (threadIdx.x == 0) {
        float m = -1e30f;
        for (int i = 0; i < NT; i++) m = fmaxf(m, att[i]);
        float e[NT], s = 0.f;
        for (int i = 0; i < NT; i++) { e[i] = __expf(att[i] - m); s += e[i]; }
        float inv = 0.5f / s;                    // fold the 0.5 of (1-tz)/2 here
        for (int i = 0; i < NT; i++) g_p[i] = e[i] * inv;
    }

#pragma unroll
    for (int i = warp; i < 2 * NH; i += 8) {
        int gate = i >> 5;                       // 0 = z gate, 1 = h gate
        int h = i & 31;
        const float* cw = gate ? chw : czw;
        const float* cb = gate ? chb : czb;
        const float* lw = gate ? lhw : lzw;
        const float* lb = gate ? lhb : lzb;
        float w = lw[lane * NH + h];             // only first NH rows matter (H0=0)
        float m0 = cw[lane] * w;
        float m1 = cw[NH + lane] * w;
        float c  = cb[lane] * w;
#pragma unroll
        for (int off = 16; off; off >>= 1) {
            m0 += __shfl_xor_sync(0xffffffffu, m0, off);
            m1 += __shfl_xor_sync(0xffffffffu, m1, off);
            c  += __shfl_xor_sync(0xffffffffu, c, off);
        }
        if (lane == 0) {
            c += lb[h];
            if (gate == 0) {                     // negate: tanh(-az/2) = -tz
                g_Mz[h] = -0.5f * m0; g_Mz[NH + h] = -0.5f * m1; g_cz[h] = -0.5f * c;
            } else {
                g_Mh[h] = m0; g_Mh[NH + h] = m1; g_ch[h] = c;
            }
        }
    }
}

__global__ void k_deg(const int* __restrict__ ei) {
    int e = blockIdx.x * blockDim.x + threadIdx.x;
    if (e < NE) atomicAdd(&g_deg[ei[NE + e]], 1.0f);
}

// After deg is final: fill per-dst buckets with (src, norm). One pass.
__global__ void k_fill(const int* __restrict__ ei) {
    int e = blockIdx.x * blockDim.x + threadIdx.x;
    if (e >= NE) return;
    int s = __ldg(ei + e);
    int d = __ldg(ei + NE + e);
    float norm = rsqrtf(g_deg[s]) * rsqrtf(g_deg[d]);
    int pos = atomicAdd(&g_cnt[d], 1);
    g_bkt[(size_t)d * CAP + pos] = make_uint2((unsigned)s, __float_as_uint(norm));
}

// Pull-gather: one warp per NODE, covering all 4 batches.
// lane = b*6 + quad (24 active lanes); each lane owns one float4 of y.
// Ragged tail handled by zeroing norms (tail slots are never-written zeros,
// so src=0 -> valid address, contribution masked to 0). No padding kernel.
__global__ void __launch_bounds__(256)
k_gather(const float* __restrict__ x) {
    int n    = blockIdx.x * 8 + (threadIdx.x >> 5);
    int lane = threadIdx.x & 31;
    if (n >= NN) return;
    bool act = lane < 24;
    int q = lane % 6;
    int b = act ? (lane / 6) : 0;

    float inv = __fdividef(1.0f, g_deg[n]);
    int   cnt = g_cnt[n];
    const uint4* bp4 = (const uint4*)(g_bkt + (size_t)n * CAP);
    const float4* x4 = (const float4*)x;

    size_t self = ((size_t)b * NN + n) * NQ + q;
    float4 acc = make_float4(0.f, 0.f, 0.f, 0.f);
    if (act) {
        float4 xs = __ldg(x4 + self);
        acc.x = xs.x * inv; acc.y = xs.y * inv;
        acc.z = xs.z * inv; acc.w = xs.w * inv;
    }

    int rc = (cnt + 3) >> 2;                      // groups of 4 entries
    for (int g = 0; g < rc; g++) {
        uint4 pa = bp4[2 * g];                    // entries 4g, 4g+1 (uniform)
        uint4 pb = bp4[2 * g + 1];                // entries 4g+2, 4g+3
        int base = 4 * g;
        float n0 = __uint_as_float(pa.y);
        float n1 = (base + 1 < cnt) ? __uint_as_float(pa.w) : 0.f;
        float n2 = (base + 2 < cnt) ? __uint_as_float(pb.y) : 0.f;
        float n3 = (base + 3 < cnt) ? __uint_as_float(pb.w) : 0.f;
        if (act) {
            size_t rowb = (size_t)b * NN;
            float4 v0 = __ldg(x4 + (rowb + pa.x) * NQ + q);
            float4 v1 = __ldg(x4 + (rowb + pa.z) * NQ + q);
            float4 v2 = __ldg(x4 + (rowb + pb.x) * NQ + q);
            float4 v3 = __ldg(x4 + (rowb + pb.z) * NQ + q);
            acc.x = fmaf(n0, v0.x, acc.x); acc.y = fmaf(n0, v0.y, acc.y);
            acc.z = fmaf(n0, v0.z, acc.z); acc.w = fmaf(n0, v0.w, acc.w);
            acc.x = fmaf(n1, v1.x, acc.x); acc.y = fmaf(n1, v1.y, acc.y);
            acc.z = fmaf(n1, v1.z, acc.z); acc.w = fmaf(n1, v1.w, acc.w);
            acc.x = fmaf(n2, v2.x, acc.x); acc.y = fmaf(n2, v2.y, acc.y);
            acc.z = fmaf(n2, v2.z, acc.z); acc.w = fmaf(n2, v2.w, acc.w);
            acc.x = fmaf(n3, v3.x, acc.x); acc.y = fmaf(n3, v3.y, acc.y);
            acc.z = fmaf(n3, v3.z, acc.z); acc.w = fmaf(n3, v3.w, acc.w);
        }
    }
    if (act) ((float4*)g_y)[self] = acc;
}

// Pointwise collapse + head GEMV. One thread per (b, node).
// h-pair-major: packed consts live in registers across the t-unrolled inner
// loop. Per (t, h-pair): 4 FFMA2 + 2 cvt + 2 tanh.f16x2 + 2 HFMA2.
__global__ void __launch_bounds__(256)
k_node(const float* __restrict__ hw, const float* __restrict__ hb,
       float* __restrict__ out) {
    __shared__ u64 s_Mz0[16], s_Mz1[16], s_czp[16];
    __shared__ u64 s_Mh0[16], s_Mh1[16], s_chp[16];
    __shared__ u64 s_hwp[NH * NO / 2];            // 192: head_w packed over j
    __shared__ u64 s_hbp[NO / 2];                 // 6
    __shared__ unsigned s_ph[NT];                 // half2(p,p)
    int tid = threadIdx.x;
    if (tid < 16) {
        s_Mz0[tid] = pk(g_Mz[2 * tid], g_Mz[2 * tid + 1]);
        s_Mz1[tid] = pk(g_Mz[NH + 2 * tid], g_Mz[NH + 2 * tid + 1]);
        s_czp[tid] = pk(g_cz[2 * tid], g_cz[2 * tid + 1]);
        s_Mh0[tid] = pk(g_Mh[2 * tid], g_Mh[2 * tid + 1]);
        s_Mh1[tid] = pk(g_Mh[NH + 2 * tid], g_Mh[NH + 2 * tid + 1]);
        s_chp[tid] = pk(g_ch[2 * tid], g_ch[2 * tid + 1]);
    }
    if (tid < NT) {
        __half2 h2 = __float2half2_rn(g_p[tid]);
        s_ph[tid] = *(unsigned*)&h2;
    }
    for (int i = tid; i < NH * NO / 2; i += 256) s_hwp[i] = ((const u64*)hw)[i];
    if (tid < NO / 2) s_hbp[tid] = ((const u64*)hb)[tid];
    __syncthreads();

    int gid = blockIdx.x * 256 + tid;
    if (gid >= NB * NN) return;

    // load y, broadcast-pack each scalar into f32x2
    float yv[NODE_W];
    const float4* yp4 = (const float4*)(g_y + (size_t)gid * NODE_W);
#pragma unroll
    for (int i = 0; i < NQ; i++) {
        float4 v = yp4[i];
        yv[4 * i] = v.x; yv[4 * i + 1] = v.y; yv[4 * i + 2] = v.z; yv[4 * i + 3] = v.w;
    }
    u64 a2[NT], b2[NT];
#pragma unroll
    for (int t = 0; t < NT; t++) { a2[t] = pk(yv[t], yv[t]); b2[t] = pk(yv[NT + t], yv[NT + t]); }
    unsigned ph[NT];
#pragma unroll
    for (int t = 0; t < NT; t++) ph[t] = s_ph[t];

    u64 o2[NO / 2];
#pragma unroll
    for (int j = 0; j < NO / 2; j++) o2[j] = s_hbp[j];

#pragma unroll 1
    for (int k = 0; k < 16; k++) {                // h-pair index
        u64 mz0 = s_Mz0[k], mz1 = s_Mz1[k], czc = s_czp[k];
        u64 mh0 = s_Mh0[k], mh1 = s_Mh1[k], chc = s_chp[k];
        unsigned acc = 0;                         // half2 zero
#pragma unroll
        for (int t = 0; t < NT; t++) {
            u64 azn = fma2(a2[t], mz0, fma2(b2[t], mz1, czc));  // = -(az)/2 pair
            u64 ahp = fma2(a2[t], mh0, fma2(b2[t], mh1, chc));
            float zl, zh, hl, hh;
            upk(azn, zl, zh); upk(ahp, hl, hh);
            unsigned tzn = tanh2(cvt2(zl, zh));   // = -tz (odd fn, consts negated)
            unsigned th  = tanh2(cvt2(hl, hh));
            unsigned u   = hfma2u(tzn, th, th);   // (1 - tz) * th
            acc = hfma2u(ph[t], u, acc);
        }
        __half2 ah2 = *(__half2*)&acc;
        float rl = fmaxf(__low2float(ah2), 0.f);  // relu, h = 2k
        float rh = fmaxf(__high2float(ah2), 0.f); // h = 2k+1
        u64 rl2 = pk(rl, rl), rh2 = pk(rh, rh);
        const u64* w0 = &s_hwp[(2 * k) * (NO / 2)];
        const u64* w1 = &s_hwp[(2 * k + 1) * (NO / 2)];
#pragma unroll
        for (int j = 0; j < NO / 2; j++)
            o2[j] = fma2(rl2, w0[j], fma2(rh2, w1[j], o2[j]));
    }

    float of[NO];
#pragma unroll
    for (int j = 0; j < NO / 2; j++) upk(o2[j], of[2 * j], of[2 * j + 1]);
    float4* op4 = (float4*)(out + (size_t)gid * NO);
#pragma unroll
    for (int j = 0; j < NO / 4; j++)
        op4[j] = make_float4(of[4 * j], of[4 * j + 1], of[4 * j + 2], of[4 * j + 3]);
}

extern "C" void kernel_launch(void* const* d_in, const int* in_sizes, int n_in,
                              void* d_out, int out_size) {
    const float* x   = (const float*)d_in[0];
    const int*   ei  = (const int*)d_in[1];
    const float* att = (const float*)d_in[2];
    const float* czw = (const float*)d_in[3];
    const float* czb = (const float*)d_in[4];
    const float* lzw = (const float*)d_in[5];
    const float* lzb = (const float*)d_in[6];
    // d_in[7..10] = conv_r_*, lin_r_* : dead (H0 == 0 -> H0*R == 0)
    const float* chw = (const float*)d_in[11];
    const float* chb = (const float*)d_in[12];
    const float* lhw = (const float*)d_in[13];
    const float* lhb = (const float*)d_in[14];
    const float* hw  = (const float*)d_in[15];
    const float* hb  = (const float*)d_in[16];
    float* out = (float*)d_out;

    k_init<<<DEG_BLOCKS + 1, 256>>>(att, czw, czb, lzw, lzb, chw, chb, lhw, lhb);
    k_deg<<<(NE + 255) / 256, 256>>>(ei);
    k_fill<<<(NE + 255) / 256, 256>>>(ei);

    k_gather<<<(NN + 7) / 8, 256>>>(x);           // warp per node

    k_node<<<(NB * NN + 255) / 256, 256>>>(hw, hb, out);
}

// round 6
// speedup vs baseline: 1.3522x; 1.0005x over previous
#include <cuda_runtime.h>
#include <cuda_fp16.h>

// ---------------------------------------------------------------------------
// Collapsed TemporalGNN (H0 == 0 in the scan; R gate dead):
//   y    = A_hat x           (pull-gather via per-dst buckets, no atomics)
//   Hn   = (1 + tanh(-(y@Mz + cz)/2)) * tanh(y@Mh + ch) * 0.5
//   acc  = sum_t p_t * Hn ;  out = relu(acc) @ head_w + head_b
// deg[d] == cnt[d] + 1 (self loops), so no separate degree pass.
// k_fused: gather (24 lanes, float4/lane) -> shuffle redistribution ->
// node math (8 lanes/batch x 2 h-pairs, FFMA2 + tanh.approx.f16x2) ->
// head GEMV butterfly reduction. y never touches memory.
// ---------------------------------------------------------------------------

#define NB 4
#define NT 12
#define NN 30000
#define NH 32
#define NO 12
#define NE 240000
#define NODE_W 24               /* F_IN(2) * T(12) floats per (b,node) */
#define NQ (NODE_W / 4)         /* 6 float4 per (b,node) */
#define CAP 64                  /* bucket capacity >> max in-degree (~30) */
#define CNT_BLOCKS ((NN + 255) / 256)

typedef unsigned long long u64;

__device__ int      g_cnt[NN];
__device__ unsigned g_bkt[(size_t)NN * CAP];  // src ids only
__device__ float g_Mz[2 * NH];                // NEGATED, x0.5
__device__ float g_Mh[2 * NH];
__device__ float g_cz[NH];                    // NEGATED, x0.5
__device__ float g_ch[NH];
__device__ float g_p[NT];                     // softmax * 0.5

// ---- packed-math helpers ----
__device__ __forceinline__ u64 pk(float lo, float hi) {
    u64 r; asm("mov.b64 %0, {%1, %2};" : "=l"(r) : "f"(lo), "f"(hi)); return r;
}
__device__ __forceinline__ void upk(u64 v, float& lo, float& hi) {
    asm("mov.b64 {%0, %1}, %2;" : "=f"(lo), "=f"(hi) : "l"(v));
}
__device__ __forceinline__ u64 fma2(u64 a, u64 b, u64 c) {
    u64 r; asm("fma.rn.f32x2 %0, %1, %2, %3;" : "=l"(r) : "l"(a), "l"(b), "l"(c));
    return r;
}
__device__ __forceinline__ u64 add2(u64 a, u64 b) {
    u64 r; asm("add.rn.f32x2 %0, %1, %2;" : "=l"(r) : "l"(a), "l"(b)); return r;
}
__device__ __forceinline__ unsigned cvt2(float lo, float hi) {   // -> f16x2
    unsigned r; asm("cvt.rn.f16x2.f32 %0, %1, %2;" : "=r"(r) : "f"(hi), "f"(lo));
    return r;
}
__device__ __forceinline__ unsigned tanh2(unsigned x) {
    unsigned r; asm("tanh.approx.f16x2 %0, %1;" : "=r"(r) : "r"(x)); return r;
}
__device__ __forceinline__ unsigned hfma2u(unsigned a, unsigned b, unsigned c) {
    unsigned r; asm("fma.rn.f16x2 %0, %1, %2, %3;" : "=r"(r) : "r"(a), "r"(b), "r"(c));
    return r;
}

// Blocks [0, CNT_BLOCKS): cnt = 0. Block CNT_BLOCKS: fused weights + softmax.
__global__ void k_init(const float* __restrict__ att,
                       const float* __restrict__ czw, const float* __restrict__ czb,
                       const float* __restrict__ lzw, const float* __restrict__ lzb,
                       const float* __restrict__ chw, const float* __restrict__ chb,
                       const float* __restrict__ lhw, const float* __restrict__ lhb) {
    if (blockIdx.x < CNT_BLOCKS) {
        int i = blockIdx.x * 256 + threadIdx.x;
        if (i < NN) g_cnt[i] = 0;
        return;
    }
    int lane = threadIdx.x & 31;
    int warp = threadIdx.x >> 5;

    if (threadIdx.x == 0) {
        float m = -1e30f;
        for (int i = 0; i < NT; i++) m = fmaxf(m, att[i]);
        float e[NT], s = 0.f;
        for (int i = 0; i < NT; i++) { e[i] = __expf(att[i] - m); s += e[i]; }
        float inv = 0.5f / s;                    // fold the 0.5 of (1-tz)/2 here
        for (int i = 0; i < NT; i++) g_p[i] = e[i] * inv;
    }

#pragma unroll
    for (int i = warp; i < 2 * NH; i += 8) {
        int gate = i >> 5;                       // 0 = z gate, 1 = h gate
        int h = i & 31;
        const float* cw = gate ? chw : czw;
        const float* cb = gate ? chb : czb;
        const float* lw = gate ? lhw : lzw;
        const float* lb = gate ? lhb : lzb;
        float w = lw[lane * NH + h];             // only first NH rows matter (H0=0)
        float m0 = cw[lane] * w;
        float m1 = cw[NH + lane] * w;
        float c  = cb[lane] * w;
#pragma unroll
        for (int off = 16; off; off >>= 1) {
            m0 += __shfl_xor_sync(0xffffffffu, m0, off);
            m1 += __shfl_xor_sync(0xffffffffu, m1, off);
            c  += __shfl_xor_sync(0xffffffffu, c, off);
        }
        if (lane == 0) {
            c += lb[h];
            if (gate == 0) {                     // negate: tanh(-az/2) = -tz
                g_Mz[h] = -0.5f * m0; g_Mz[NH + h] = -0.5f * m1; g_cz[h] = -0.5f * c;
            } else {
                g_Mh[h] = m0; g_Mh[NH + h] = m1; g_ch[h] = c;
            }
        }
    }
}

// One pass over edges: count in-degree and push src into dst's bucket.
__global__ void k_fill(const int* __restrict__ ei) {
    int e = blockIdx.x * blockDim.x + threadIdx.x;
    if (e >= NE) return;
    int s = __ldg(ei + e);
    int d = __ldg(ei + NE + e);
    int pos = atomicAdd(&g_cnt[d], 1);
    g_bkt[(size_t)d * CAP + pos] = (unsigned)s;
}

// Fused gather + node compute + head GEMV. One warp per node, all 4 batches.
__global__ void __launch_bounds__(256)
k_fused(const float* __restrict__ x, const float* __restrict__ hw,
        const float* __restrict__ hb, float* __restrict__ out) {
    __shared__ u64 s_Mz0[16], s_Mz1[16], s_czp[16];
    __shared__ u64 s_Mh0[16], s_Mh1[16], s_chp[16];
    __shared__ u64 s_hwp[NH * NO / 2];            // head_w packed over j
    __shared__ u64 s_hbp[NO / 2];
    __shared__ unsigned s_ph[NT];                 // half2(p,p)
    int tid = threadIdx.x;
    if (tid < 16) {
        s_Mz0[tid] = pk(g_Mz[2 * tid], g_Mz[2 * tid + 1]);
        s_Mz1[tid] = pk(g_Mz[NH + 2 * tid], g_Mz[NH + 2 * tid + 1]);
        s_czp[tid] = pk(g_cz[2 * tid], g_cz[2 * tid + 1]);
        s_Mh0[tid] = pk(g_Mh[2 * tid], g_Mh[2 * tid + 1]);
        s_Mh1[tid] = pk(g_Mh[NH + 2 * tid], g_Mh[NH + 2 * tid + 1]);
        s_chp[tid] = pk(g_ch[2 * tid], g_ch[2 * tid + 1]);
    }
    if (tid < NT) {
        __half2 h2 = __float2half2_rn(g_p[tid]);
        s_ph[tid] = *(unsigned*)&h2;
    }
    for (int i = tid; i < NH * NO / 2; i += 256) s_hwp[i] = ((const u64*)hw)[i];
    if (tid < NO / 2) s_hbp[tid] = ((const u64*)hb)[tid];
    __syncthreads();

    int n    = blockIdx.x * 8 + (tid >> 5);       // NN % 8 == 0: all warps valid
    int lane = tid & 31;

    // ---------------- gather phase: 24 active lanes, lane = b*6 + q ---------
    bool act = lane < 24;
    int q = lane % 6;
    int b = act ? (lane / 6) : 0;

    int   cnt  = g_cnt[n];
    float dinv = rsqrtf((float)(cnt + 1));        // deg = cnt + 1 (self loop)
    const uint4*  bp4 = (const uint4*)(g_bkt + (size_t)n * CAP);
    const float4* x4  = (const float4*)x;

    float4 acc = make_float4(0.f, 0.f, 0.f, 0.f);
    if (act) {
        float4 xs = __ldg(x4 + ((size_t)b * NN + n) * NQ + q);
        float inv = dinv * dinv;                  // 1/deg self-loop weight
        acc.x = xs.x * inv; acc.y = xs.y * inv;
        acc.z = xs.z * inv; acc.w = xs.w * inv;
    }

    int rc = (cnt + 3) >> 2;                      // groups of 4 bucket entries
    for (int g = 0; g < rc; g++) {
        uint4 pa = bp4[g];                        // 4 src ids (lane-uniform)
        int base = 4 * g;
        float n0 = dinv * rsqrtf((float)(g_cnt[pa.x] + 1));
        float n1 = (base + 1 < cnt) ? dinv * rsqrtf((float)(g_cnt[pa.y] + 1)) : 0.f;
        float n2 = (base + 2 < cnt) ? dinv * rsqrtf((float)(g_cnt[pa.z] + 1)) : 0.f;
        float n3 = (base + 3 < cnt) ? dinv * rsqrtf((float)(g_cnt[pa.w] + 1)) : 0.f;
        if (act) {
            size_t rowb = (size_t)b * NN;
            float4 v0 = __ldg(x4 + (rowb + pa.x) * NQ + q);
            float4 v1 = __ldg(x4 + (rowb + pa.y) * NQ + q);
            float4 v2 = __ldg(x4 + (rowb + pa.z) * NQ + q);
            float4 v3 = __ldg(x4 + (rowb + pa.w) * NQ + q);
            acc.x = fmaf(n0, v0.x, acc.x); acc.y = fmaf(n0, v0.y, acc.y);
            acc.z = fmaf(n0, v0.z, acc.z); acc.w = fmaf(n0, v0.w, acc.w);
            acc.x = fmaf(n1, v1.x, acc.x); acc.y = fmaf(n1, v1.y, acc.y);
            acc.z = fmaf(n1, v1.z, acc.z); acc.w = fmaf(n1, v1.w, acc.w);
            acc.x = fmaf(n2, v2.x, acc.x); acc.y = fmaf(n2, v2.y, acc.y);
            acc.z = fmaf(n2, v2.z, acc.z); acc.w = fmaf(n2, v2.w, acc.w);
            acc.x = fmaf(n3, v3.x, acc.x); acc.y = fmaf(n3, v3.y, acc.y);
            acc.z = fmaf(n3, v3.z, acc.z); acc.w = fmaf(n3, v3.w, acc.w);
        }
    }

    // -------- redistribute via shuffles: lane = b*8 + r, r in [0,8) --------
    // y[b][j] lives in lane b*6 + j/4, component j%4.
    float ar[4] = {acc.x, acc.y, acc.z, acc.w};
    int r  = lane & 7;
    int bb = lane >> 3;
    float ya[NT], yb[NT];
#pragma unroll
    for (int t = 0; t < NT; t++) {
        ya[t] = __shfl_sync(0xffffffffu, ar[t & 3], bb * 6 + (t >> 2));
        yb[t] = __shfl_sync(0xffffffffu, ar[t & 3], bb * 6 + 3 + (t >> 2));
    }

    // -------- node phase: lane handles h-pairs 2r, 2r+1 (h = 4r..4r+3) -----
    int k0 = 2 * r;
    u64 mz0A = s_Mz0[k0], mz1A = s_Mz1[k0], czA = s_czp[k0];
    u64 mh0A = s_Mh0[k0], mh1A = s_Mh1[k0], chA = s_chp[k0];
    u64 mz0B = s_Mz0[k0 + 1], mz1B = s_Mz1[k0 + 1], czB = s_czp[k0 + 1];
    u64 mh0B = s_Mh0[k0 + 1], mh1B = s_Mh1[k0 + 1], chB = s_chp[k0 + 1];
    unsigned ph_[NT];
#pragma unroll
    for (int t = 0; t < NT; t++) ph_[t] = s_ph[t];

    unsigned accA = 0, accB = 0;                  // half2 zeros
#pragma unroll
    for (int t = 0; t < NT; t++) {
        u64 a2 = pk(ya[t], ya[t]);
        u64 b2 = pk(yb[t], yb[t]);
        u64 aznA = fma2(a2, mz0A, fma2(b2, mz1A, czA));  // = -(az)/2 pair
        u64 ahpA = fma2(a2, mh0A, fma2(b2, mh1A, chA));
        u64 aznB = fma2(a2, mz0B, fma2(b2, mz1B, czB));
        u64 ahpB = fma2(a2, mh0B, fma2(b2, mh1B, chB));
        float zl, zh, hl, hh;
        upk(aznA, zl, zh); upk(ahpA, hl, hh);
        unsigned tznA = tanh2(cvt2(zl, zh));      // = -tz (odd fn, consts negated)
        unsigned thA  = tanh2(cvt2(hl, hh));
        upk(aznB, zl, zh); upk(ahpB, hl, hh);
        unsigned tznB = tanh2(cvt2(zl, zh));
        unsigned thB  = tanh2(cvt2(hl, hh));
        accA = hfma2u(ph_[t], hfma2u(tznA, thA, thA), accA);
        accB = hfma2u(ph_[t], hfma2u(tznB, thB, thB), accB);
    }

    // -------- head GEMV: partials over this lane's 4 h, butterfly over 8 ---
    __half2 hA = *(__half2*)&accA, hB = *(__half2*)&accB;
    float r0 = fmaxf(__low2float(hA), 0.f);
    float r1 = fmaxf(__high2float(hA), 0.f);
    float r2 = fmaxf(__low2float(hB), 0.f);
    float r3 = fmaxf(__high2float(hB), 0.f);
    u64 r02 = pk(r0, r0), r12 = pk(r1, r1), r22 = pk(r2, r2), r32 = pk(r3, r3);
    const u64* w0 = &s_hwp[(4 * r + 0) * (NO / 2)];
    const u64* w1 = &s_hwp[(4 * r + 1) * (NO / 2)];
    const u64* w2 = &s_hwp[(4 * r + 2) * (NO / 2)];
    const u64* w3 = &s_hwp[(4 * r + 3) * (NO / 2)];
    u64 o2[NO / 2];
#pragma unroll
    for (int j = 0; j < NO / 2; j++)
        o2[j] = fma2(r02, w0[j], fma2(r12, w1[j], fma2(r22, w2[j], fma2(r32, w3[j], 0ULL))));

#pragma unroll
    for (int off = 1; off < 8; off <<= 1) {
#pragma unroll
        for (int j = 0; j < NO / 2; j++)
            o2[j] = add2(o2[j], __shfl_xor_sync(0xffffffffu, o2[j], off));
    }

    if (r < 3) {
        float4 v;
        upk(add2(o2[2 * r], s_hbp[2 * r]), v.x, v.y);
        upk(add2(o2[2 * r + 1], s_hbp[2 * r + 1]), v.z, v.w);
        ((float4*)out)[((size_t)bb * NN + n) * 3 + r] = v;
    }
}

extern "C" void kernel_launch(void* const* d_in, const int* in_sizes, int n_in,
                              void* d_out, int out_size) {
    const float* x   = (const float*)d_in[0];
    const int*   ei  = (const int*)d_in[1];
    const float* att = (const float*)d_in[2];
    const float* czw = (const float*)d_in[3];
    const float* czb = (const float*)d_in[4];
    const float* lzw = (const float*)d_in[5];
    const float* lzb = (const float*)d_in[6];
    // d_in[7..10] = conv_r_*, lin_r_* : dead (H0 == 0 -> H0*R == 0)
    const float* chw = (const float*)d_in[11];
    const float* chb = (const float*)d_in[12];
    const float* lhw = (const float*)d_in[13];
    const float* lhb = (const float*)d_in[14];
    const float* hw  = (const float*)d_in[15];
    const float* hb  = (const float*)d_in[16];
    float* out = (float*)d_out;

    k_init<<<CNT_BLOCKS + 1, 256>>>(att, czw, czb, lzw, lzb, chw, chb, lhw, lhb);
    k_fill<<<(NE + 255) / 256, 256>>>(ei);
    k_fused<<<NN / 8, 256>>>(x, hw, hb, out);     // warp per node
}